// round 3
// baseline (speedup 1.0000x reference)
#include <cuda_runtime.h>
#include <math.h>

#define NHEAD 32
#define DDIM  128
#define KVLEN 32768
#define PAGE  16
#define NPAGE 2048
#define TOPK  256
#define NSEL  (TOPK * PAGE)          /* 4096 selected tokens per head */
#define HDIM  4096
#define SCALE 0.08838834764831845f   /* 1/sqrt(128) */

// ---------------- scratch (device globals; no allocations allowed) ----------
__device__ float g_qkv[3 * HDIM];        // q | k_new | v_new (q,k post-RoPE)
__device__ float g_sall[NHEAD * KVLEN];  // all scores, scaled (4 MB)
__device__ float g_est[NHEAD * NPAGE];   // page estimates
__device__ float g_w[NHEAD * NSEL];      // softmax weights of selected tokens
__device__ int   g_ti[NHEAD * NSEL];     // token ids of selected tokens
__device__ float g_o[NHEAD * DDIM];      // attention output

// ---------------- 0: zero atomic targets ------------------------------------
__global__ void k_init(float* __restrict__ out) {
    int t = blockIdx.x * blockDim.x + threadIdx.x;
    if (t < 3 * HDIM) g_qkv[t] = 0.f;
    if (t < HDIM)     out[t]   = 0.f;
}

// ---------------- 1: fused QKV GEMV (split-K, atomic accumulate) ------------
// grid = 3 mats * 32 colgroups * 8 rowgroups = 768 blocks, 128 threads
__global__ void k_qkv(const float* __restrict__ x,
                      const float* __restrict__ Wq,
                      const float* __restrict__ Wk,
                      const float* __restrict__ Wv) {
    int b  = blockIdx.x;
    int m  = b >> 8;           // matrix 0..2
    int r  = b & 255;
    int cg = r & 31;           // column group (128 cols)
    int rg = r >> 5;           // row group (512 rows)
    const float* W = (m == 0) ? Wq : (m == 1) ? Wk : Wv;

    int lane = threadIdx.x & 31;
    int wrp  = threadIdx.x >> 5;   // 4 warps, 128 rows each

    __shared__ float xs[512];
    for (int i = threadIdx.x; i < 512; i += 128) xs[i] = x[rg * 512 + i];
    __syncthreads();

    int col4 = cg * 32 + lane;               // float4 column index (0..1023)
    long i0  = (long)rg * 512 + wrp * 128;
    const float4* W4 = (const float4*)W;

    float4 acc = make_float4(0.f, 0.f, 0.f, 0.f);
#pragma unroll 16
    for (int i = 0; i < 128; i++) {
        float  xv = xs[wrp * 128 + i];
        float4 wv = __ldg(&W4[(i0 + i) * 1024 + col4]);
        acc.x += xv * wv.x; acc.y += xv * wv.y;
        acc.z += xv * wv.z; acc.w += xv * wv.w;
    }
    float* dst = &g_qkv[m * HDIM + col4 * 4];
    atomicAdd(dst + 0, acc.x); atomicAdd(dst + 1, acc.y);
    atomicAdd(dst + 2, acc.z); atomicAdd(dst + 3, acc.w);
}

// ---------------- 2: RoPE on q and k_new (pos = 32768) ----------------------
__global__ void k_rope() {
    int t = blockIdx.x * blockDim.x + threadIdx.x;   // 0..2047
    if (t >= NHEAD * 64) return;
    int h = t >> 6, i = t & 63;
    float inv = (float)pow(10000.0, -(double)i / 64.0);
    float ang = 32768.0f * inv;
    float s, c;
    sincosf(ang, &s, &c);
#pragma unroll
    for (int m = 0; m < 2; m++) {
        float* buf = &g_qkv[m * HDIM + h * DDIM];
        float a = buf[i], bb = buf[i + 64];
        buf[i]      = a * c - bb * s;
        buf[i + 64] = bb * c + a * s;
    }
}

// ---------------- 3: page min/max + est + ALL token scores (one pass) -------
// one warp per (page, head); grid 8192 x 256 threads
__global__ void __launch_bounds__(256) k_scan(const float* __restrict__ kc) {
    int g    = blockIdx.x * 8 + (threadIdx.x >> 5);
    int lane = threadIdx.x & 31;
    int p = g >> 5, h = g & 31;

    const float4* k4 = (const float4*)kc;
    float4 q4 = ((const float4*)g_qkv)[h * 32 + lane];   // q[h, lane*4..+3]

    long base = ((long)p * 16 * 32 + h) * 32 + lane;     // float4 offset
    float4 mn = make_float4( 1e30f,  1e30f,  1e30f,  1e30f);
    float4 mx = make_float4(-1e30f, -1e30f, -1e30f, -1e30f);

#pragma unroll
    for (int tb = 0; tb < 4; tb++) {
        float4 k0 = __ldg(&k4[base + (long)(tb * 4 + 0) * 1024]);
        float4 k1 = __ldg(&k4[base + (long)(tb * 4 + 1) * 1024]);
        float4 k2 = __ldg(&k4[base + (long)(tb * 4 + 2) * 1024]);
        float4 k3 = __ldg(&k4[base + (long)(tb * 4 + 3) * 1024]);

        mn.x = fminf(fminf(fminf(mn.x, k0.x), fminf(k1.x, k2.x)), k3.x);
        mn.y = fminf(fminf(fminf(mn.y, k0.y), fminf(k1.y, k2.y)), k3.y);
        mn.z = fminf(fminf(fminf(mn.z, k0.z), fminf(k1.z, k2.z)), k3.z);
        mn.w = fminf(fminf(fminf(mn.w, k0.w), fminf(k1.w, k2.w)), k3.w);
        mx.x = fmaxf(fmaxf(fmaxf(mx.x, k0.x), fmaxf(k1.x, k2.x)), k3.x);
        mx.y = fmaxf(fmaxf(fmaxf(mx.y, k0.y), fmaxf(k1.y, k2.y)), k3.y);
        mx.z = fmaxf(fmaxf(fmaxf(mx.z, k0.z), fmaxf(k1.z, k2.z)), k3.z);
        mx.w = fmaxf(fmaxf(fmaxf(mx.w, k0.w), fmaxf(k1.w, k2.w)), k3.w);

        float d0 = q4.x * k0.x + q4.y * k0.y + q4.z * k0.z + q4.w * k0.w;
        float d1 = q4.x * k1.x + q4.y * k1.y + q4.z * k1.z + q4.w * k1.w;
        float d2 = q4.x * k2.x + q4.y * k2.y + q4.z * k2.z + q4.w * k2.w;
        float d3 = q4.x * k3.x + q4.y * k3.y + q4.z * k3.z + q4.w * k3.w;
#pragma unroll
        for (int o = 16; o > 0; o >>= 1) {
            d0 += __shfl_xor_sync(0xffffffffu, d0, o);
            d1 += __shfl_xor_sync(0xffffffffu, d1, o);
            d2 += __shfl_xor_sync(0xffffffffu, d2, o);
            d3 += __shfl_xor_sync(0xffffffffu, d3, o);
        }
        if (lane == 0) {
            float4 sv = make_float4(d0 * SCALE, d1 * SCALE, d2 * SCALE, d3 * SCALE);
            *(float4*)&g_sall[h * KVLEN + p * 16 + tb * 4] = sv;
        }
    }
    float e = fmaxf(q4.x * mn.x, q4.x * mx.x) + fmaxf(q4.y * mn.y, q4.y * mx.y)
            + fmaxf(q4.z * mn.z, q4.z * mx.z) + fmaxf(q4.w * mn.w, q4.w * mx.w);
#pragma unroll
    for (int o = 16; o > 0; o >>= 1) e += __shfl_xor_sync(0xffffffffu, e, o);
    if (lane == 0) g_est[h * NPAGE + p] = e;
}

// ---------------- 4: fused radix-select top-256 + softmax + weights ----------
// 32 blocks (one per head) x 256 threads
__global__ void k_sel() {
    int h = blockIdx.x, tid = threadIdx.x;
    __shared__ unsigned keys[NPAGE];    // 8 KB
    __shared__ int      cnt[256];
    __shared__ float    sval[NSEL];     // 16 KB
    __shared__ int      sel[TOPK];
    __shared__ float    red[256];
    __shared__ unsigned sh_prefix;
    __shared__ int      sh_krem, sh_cntGT, sh_base;

    // load est -> order-preserving uint keys (descending fp == descending uint)
    for (int i = tid; i < NPAGE; i += 256) {
        unsigned u = __float_as_uint(g_est[h * NPAGE + i]);
        keys[i] = (u & 0x80000000u) ? ~u : (u | 0x80000000u);
    }
    if (tid == 0) { sh_prefix = 0u; sh_krem = TOPK; sh_cntGT = 0; sh_base = 0; }
    __syncthreads();

    // 4-round radix select: find T = 256th-largest key
#pragma unroll
    for (int shift = 24; shift >= 0; shift -= 8) {
        cnt[tid] = 0;
        __syncthreads();
        unsigned pmask = (shift == 24) ? 0u : (0xFFFFFFFFu << (shift + 8));
        unsigned pfx = sh_prefix;
        for (int i = tid; i < NPAGE; i += 256)
            if ((keys[i] & pmask) == pfx)
                atomicAdd(&cnt[(keys[i] >> shift) & 255], 1);
        __syncthreads();
        if (tid == 0) {
            int krem = sh_krem, c = 0, d;
            for (d = 255; d > 0; d--) {
                if (c + cnt[d] >= krem) break;
                c += cnt[d];
            }
            sh_krem = krem - c;
            sh_prefix = pfx | ((unsigned)d << shift);
        }
        __syncthreads();
    }
    unsigned T = sh_prefix;

    // count strictly greater, collect them (order irrelevant), pad ties by index
    int local = 0;
    for (int i = tid; i < NPAGE; i += 256) if (keys[i] > T) local++;
    atomicAdd(&sh_cntGT, local);
    __syncthreads();
    int cntGT = sh_cntGT;
    for (int i = tid; i < NPAGE; i += 256)
        if (keys[i] > T) sel[atomicAdd(&sh_base, 1)] = i;
    __syncthreads();
    if (tid == 0) {
        int pos = cntGT;
        for (int i = 0; i < NPAGE && pos < TOPK; i++)
            if (keys[i] == T) sel[pos++] = i;
    }
    __syncthreads();

    // s_new = (q . k_new) * SCALE
    red[tid] = (tid < 128) ? g_qkv[h * DDIM + tid] * g_qkv[HDIM + h * DDIM + tid] : 0.f;
    __syncthreads();
    for (int o = 128; o > 0; o >>= 1) {
        if (tid < o) red[tid] += red[tid + o];
        __syncthreads();
    }
    float s_new = red[0] * SCALE;
    __syncthreads();

    // gather the 4096 selected scores into shared
    for (int j = tid; j < NSEL; j += 256)
        sval[j] = g_sall[h * KVLEN + sel[j >> 4] * 16 + (j & 15)];
    __syncthreads();

    // max
    float lm = s_new;
    for (int j = tid; j < NSEL; j += 256) lm = fmaxf(lm, sval[j]);
    red[tid] = lm;
    __syncthreads();
    for (int o = 128; o > 0; o >>= 1) {
        if (tid < o) red[tid] = fmaxf(red[tid], red[tid + o]);
        __syncthreads();
    }
    float m = red[0];
    __syncthreads();

    // Z
    float z = (tid == 0) ? expf(s_new - m) : 0.f;
    for (int j = tid; j < NSEL; j += 256) z += expf(sval[j] - m);
    red[tid] = z;
    __syncthreads();
    for (int o = 128; o > 0; o >>= 1) {
        if (tid < o) red[tid] += red[tid + o];
        __syncthreads();
    }
    float zi = 1.f / red[0];
    __syncthreads();

    // emit weights + token ids; init o with new-token contribution
    for (int j = tid; j < NSEL; j += 256) {
        g_w[h * NSEL + j]  = expf(sval[j] - m) * zi;
        g_ti[h * NSEL + j] = sel[j >> 4] * 16 + (j & 15);
    }
    if (tid < 128)
        g_o[h * DDIM + tid] = expf(s_new - m) * zi * g_qkv[2 * HDIM + h * DDIM + tid];
}

// ---------------- 5: weighted V gather-accumulate ----------------------------
// grid = 32 heads * 16 chunks; 256 threads; each warp covers full dim in float4
__global__ void __launch_bounds__(256) k_av(const float* __restrict__ vc) {
    int b = blockIdx.x;
    int h = b >> 4, ch = b & 15;
    int tid = threadIdx.x, lane = tid & 31, wid = tid >> 5;
    const float4* v4 = (const float4*)vc;

    int jbase = h * NSEL + ch * 256 + wid * 32;   // 32 tokens per warp
    float4 acc = make_float4(0.f, 0.f, 0.f, 0.f);
#pragma unroll 4
    for (int t = 0; t < 32; t++) {
        int   tok = g_ti[jbase + t];
        float w   = g_w[jbase + t];
        float4 vv = __ldg(&v4[((long)tok * 32 + h) * 32 + lane]);
        acc.x += w * vv.x; acc.y += w * vv.y;
        acc.z += w * vv.z; acc.w += w * vv.w;
    }
    __shared__ float sacc[8][128];
    ((float4*)sacc[wid])[lane] = acc;
    __syncthreads();
    if (tid < 128) {
        float s = 0.f;
#pragma unroll
        for (int w2 = 0; w2 < 8; w2++) s += sacc[w2][tid];
        atomicAdd(&g_o[h * DDIM + tid], s);
    }
}

// ---------------- 6: output GEMV (split-K, atomic) ---------------------------
// grid = 32 colgroups * 16 rowgroups = 512 blocks, 128 threads
__global__ void k_out(const float* __restrict__ Wo, float* __restrict__ out) {
    int b  = blockIdx.x;
    int cg = b & 31;
    int rg = b >> 5;               // 16 rowgroups of 256 rows
    int lane = threadIdx.x & 31;
    int wrp  = threadIdx.x >> 5;   // 4 warps, 64 rows each

    __shared__ float os[256];
    for (int i = threadIdx.x; i < 256; i += 128) os[i] = g_o[rg * 256 + i];
    __syncthreads();

    long i0  = (long)rg * 256 + wrp * 64;
    int col4 = cg * 32 + lane;
    const float4* W4 = (const float4*)Wo;
    float4 acc = make_float4(0.f, 0.f, 0.f, 0.f);
#pragma unroll 16
    for (int i = 0; i < 64; i++) {
        float  xv = os[wrp * 64 + i];
        float4 wv = __ldg(&W4[(i0 + i) * 1024 + col4]);
        acc.x += xv * wv.x; acc.y += xv * wv.y;
        acc.z += xv * wv.z; acc.w += xv * wv.w;
    }
    float* dst = &out[col4 * 4];
    atomicAdd(dst + 0, acc.x); atomicAdd(dst + 1, acc.y);
    atomicAdd(dst + 2, acc.z); atomicAdd(dst + 3, acc.w);
}

// ---------------- launch ------------------------------------------------------
extern "C" void kernel_launch(void* const* d_in, const int* in_sizes, int n_in,
                              void* d_out, int out_size) {
    const float* x  = (const float*)d_in[0];
    const float* kc = (const float*)d_in[1];
    const float* vc = (const float*)d_in[2];
    const float* Wq = (const float*)d_in[3];
    const float* Wk = (const float*)d_in[4];
    const float* Wv = (const float*)d_in[5];
    const float* Wo = (const float*)d_in[6];
    float* out = (float*)d_out;

    k_init<<<48, 256>>>(out);
    k_qkv<<<768, 128>>>(x, Wq, Wk, Wv);
    k_rope<<<16, 128>>>();
    k_scan<<<8192, 256>>>(kc);
    k_sel<<<32, 256>>>();
    k_av<<<512, 256>>>(vc);
    k_out<<<512, 128>>>(Wo, out);
}

// round 4
// speedup vs baseline: 1.3295x; 1.3295x over previous
#include <cuda_runtime.h>
#include <math.h>

#define NHEAD 32
#define DDIM  128
#define KVLEN 32768
#define PAGE  16
#define NPAGE 2048
#define TOPK  256
#define NSEL  (TOPK * PAGE)          /* 4096 selected tokens per head */
#define HDIM  4096
#define SCALE 0.08838834764831845f   /* 1/sqrt(128) */

// ---------------- scratch (device globals; no allocations allowed) ----------
__device__ float g_qkv[3 * HDIM];        // q | k_new | v_new (q,k post-RoPE)
__device__ float g_sall[NHEAD * KVLEN];  // all scores, scaled (4 MB)
__device__ float g_est[NHEAD * NPAGE];   // page estimates
__device__ float g_w[NHEAD * NSEL];      // softmax weights of selected tokens
__device__ int   g_ti[NHEAD * NSEL];     // token ids of selected tokens
__device__ float g_o[NHEAD * DDIM];      // attention output

// ---------------- 0: zero atomic targets ------------------------------------
__global__ void k_init(float* __restrict__ out) {
    int t = blockIdx.x * blockDim.x + threadIdx.x;
    if (t < 3 * HDIM) g_qkv[t] = 0.f;
    if (t < HDIM)     out[t]   = 0.f;
}

// ---------------- 1: fused QKV GEMV (split-K, atomic accumulate) ------------
// grid = 3 mats * 32 colgroups * 8 rowgroups = 768 blocks, 128 threads
__global__ void k_qkv(const float* __restrict__ x,
                      const float* __restrict__ Wq,
                      const float* __restrict__ Wk,
                      const float* __restrict__ Wv) {
    int b  = blockIdx.x;
    int m  = b >> 8;           // matrix 0..2
    int r  = b & 255;
    int cg = r & 31;           // column group (128 cols)
    int rg = r >> 5;           // row group (512 rows)
    const float* W = (m == 0) ? Wq : (m == 1) ? Wk : Wv;

    int lane = threadIdx.x & 31;
    int wrp  = threadIdx.x >> 5;   // 4 warps, 128 rows each

    __shared__ float xs[512];
    for (int i = threadIdx.x; i < 512; i += 128) xs[i] = x[rg * 512 + i];
    __syncthreads();

    int col4 = cg * 32 + lane;               // float4 column index (0..1023)
    long i0  = (long)rg * 512 + wrp * 128;
    const float4* W4 = (const float4*)W;

    float4 acc = make_float4(0.f, 0.f, 0.f, 0.f);
#pragma unroll 8
    for (int i = 0; i < 128; i++) {
        float  xv = xs[wrp * 128 + i];
        float4 wv = __ldg(&W4[(i0 + i) * 1024 + col4]);
        acc.x += xv * wv.x; acc.y += xv * wv.y;
        acc.z += xv * wv.z; acc.w += xv * wv.w;
    }
    float* dst = &g_qkv[m * HDIM + col4 * 4];
    atomicAdd(dst + 0, acc.x); atomicAdd(dst + 1, acc.y);
    atomicAdd(dst + 2, acc.z); atomicAdd(dst + 3, acc.w);
}

// ---------------- 2: RoPE on q and k_new (pos = 32768) ----------------------
__global__ void k_rope() {
    int t = blockIdx.x * blockDim.x + threadIdx.x;   // 0..2047
    if (t >= NHEAD * 64) return;
    int h = t >> 6, i = t & 63;
    float inv = (float)pow(10000.0, -(double)i / 64.0);
    float ang = 32768.0f * inv;
    float s, c;
    sincosf(ang, &s, &c);
#pragma unroll
    for (int m = 0; m < 2; m++) {
        float* buf = &g_qkv[m * HDIM + h * DDIM];
        float a = buf[i], bb = buf[i + 64];
        buf[i]      = a * c - bb * s;
        buf[i + 64] = bb * c + a * s;
    }
}

// ---------------- 3: page min/max + est + ALL token scores (one pass) -------
// one warp per (page, head); grid 8192 x 256 threads  [R2 version, measured]
__global__ void k_scan(const float* __restrict__ kc) {
    int g    = blockIdx.x * 8 + (threadIdx.x >> 5);
    int lane = threadIdx.x & 31;
    int p = g >> 5, h = g & 31;

    const float4* k4 = (const float4*)kc;
    float4 q4 = ((const float4*)g_qkv)[h * 32 + lane];   // q[h, lane*4..+3]

    long base = ((long)p * 16 * 32 + h) * 32;            // float4 offset
    float4 mn = make_float4(0, 0, 0, 0), mx = mn;

#pragma unroll
    for (int t = 0; t < 16; t++) {
        float4 kv = __ldg(&k4[base + (long)t * 1024 + lane]);
        if (t == 0) { mn = kv; mx = kv; }
        else {
            mn.x = fminf(mn.x, kv.x); mn.y = fminf(mn.y, kv.y);
            mn.z = fminf(mn.z, kv.z); mn.w = fminf(mn.w, kv.w);
            mx.x = fmaxf(mx.x, kv.x); mx.y = fmaxf(mx.y, kv.y);
            mx.z = fmaxf(mx.z, kv.z); mx.w = fmaxf(mx.w, kv.w);
        }
        float d = q4.x * kv.x + q4.y * kv.y + q4.z * kv.z + q4.w * kv.w;
#pragma unroll
        for (int o = 16; o > 0; o >>= 1) d += __shfl_xor_sync(0xffffffffu, d, o);
        if (lane == 0) g_sall[h * KVLEN + p * 16 + t] = d * SCALE;
    }
    float e = fmaxf(q4.x * mn.x, q4.x * mx.x) + fmaxf(q4.y * mn.y, q4.y * mx.y)
            + fmaxf(q4.z * mn.z, q4.z * mx.z) + fmaxf(q4.w * mn.w, q4.w * mx.w);
#pragma unroll
    for (int o = 16; o > 0; o >>= 1) e += __shfl_xor_sync(0xffffffffu, e, o);
    if (lane == 0) g_est[h * NPAGE + p] = e;
}

// ---------------- 4: fused top-256 (parallel radix select) + softmax ---------
// 32 blocks (one per head) x 256 threads; no thread-serial loops
__global__ void k_sel() {
    int h = blockIdx.x, tid = threadIdx.x;
    __shared__ unsigned keys[NPAGE];    // 8 KB
    __shared__ int      cnt[257];
    __shared__ float    sval[NSEL];     // 16 KB
    __shared__ int      sel[TOPK];
    __shared__ float    red[256];
    __shared__ unsigned sh_prefix;
    __shared__ int      sh_krem, sh_base;

    // load est -> order-preserving uint keys (descending fp == descending uint)
    for (int i = tid; i < NPAGE; i += 256) {
        unsigned u = __float_as_uint(g_est[h * NPAGE + i]);
        keys[i] = (u & 0x80000000u) ? ~u : (u | 0x80000000u);
    }
    if (tid == 0) { sh_prefix = 0u; sh_krem = TOPK; sh_base = 0; }
    __syncthreads();

    // 4-round radix select: find T = 256th-largest key. All steps parallel.
#pragma unroll
    for (int shift = 24; shift >= 0; shift -= 8) {
        cnt[tid] = 0;
        __syncthreads();
        unsigned pmask = (shift == 24) ? 0u : (0xFFFFFFFFu << (shift + 8));
        unsigned pfx = sh_prefix;
        for (int i = tid; i < NPAGE; i += 256)
            if ((keys[i] & pmask) == pfx)
                atomicAdd(&cnt[(keys[i] >> shift) & 255], 1);
        __syncthreads();
        // suffix (descending-inclusive) sum: S[d] = sum_{e>=d} cnt[e]
        int v = cnt[tid];
        __syncthreads();
#pragma unroll
        for (int off = 1; off < 256; off <<= 1) {
            int add = (tid + off < 256) ? cnt[tid + off] : 0;
            __syncthreads();
            v += add;
            cnt[tid] = v;
            __syncthreads();
        }
        // now cnt[d] = #keys with digit >= d (within prefix group)
        int krem = sh_krem;
        int Snext = (tid < 255) ? cnt[tid + 1] : 0;
        if (Snext < krem && krem <= cnt[tid]) {   // exactly one tid satisfies
            sh_prefix = pfx | ((unsigned)tid << shift);
            sh_krem   = krem - Snext;
        }
        __syncthreads();
    }
    unsigned T = sh_prefix;

    // collect strictly-greater (all belong), then pad with ties (capped).
    for (int i = tid; i < NPAGE; i += 256)
        if (keys[i] > T) sel[atomicAdd(&sh_base, 1)] = i;
    __syncthreads();
    for (int i = tid; i < NPAGE; i += 256)
        if (keys[i] == T) {
            int p = atomicAdd(&sh_base, 1);
            if (p < TOPK) sel[p] = i;
        }
    __syncthreads();

    // s_new = (q . k_new) * SCALE
    red[tid] = (tid < 128) ? g_qkv[h * DDIM + tid] * g_qkv[HDIM + h * DDIM + tid] : 0.f;
    __syncthreads();
    for (int o = 128; o > 0; o >>= 1) {
        if (tid < o) red[tid] += red[tid + o];
        __syncthreads();
    }
    float s_new = red[0] * SCALE;
    __syncthreads();

    // gather the 4096 selected scores into shared
    for (int j = tid; j < NSEL; j += 256)
        sval[j] = g_sall[h * KVLEN + sel[j >> 4] * 16 + (j & 15)];
    __syncthreads();

    // max
    float lm = s_new;
    for (int j = tid; j < NSEL; j += 256) lm = fmaxf(lm, sval[j]);
    red[tid] = lm;
    __syncthreads();
    for (int o = 128; o > 0; o >>= 1) {
        if (tid < o) red[tid] = fmaxf(red[tid], red[tid + o]);
        __syncthreads();
    }
    float m = red[0];
    __syncthreads();

    // Z
    float z = (tid == 0) ? expf(s_new - m) : 0.f;
    for (int j = tid; j < NSEL; j += 256) z += expf(sval[j] - m);
    red[tid] = z;
    __syncthreads();
    for (int o = 128; o > 0; o >>= 1) {
        if (tid < o) red[tid] += red[tid + o];
        __syncthreads();
    }
    float zi = 1.f / red[0];
    __syncthreads();

    // emit weights + token ids; init o with new-token contribution
    for (int j = tid; j < NSEL; j += 256) {
        g_w[h * NSEL + j]  = expf(sval[j] - m) * zi;
        g_ti[h * NSEL + j] = sel[j >> 4] * 16 + (j & 15);
    }
    if (tid < 128)
        g_o[h * DDIM + tid] = expf(s_new - m) * zi * g_qkv[2 * HDIM + h * DDIM + tid];
}

// ---------------- 5: weighted V gather-accumulate (R2 structure) -------------
// grid = 32 heads * 16 chunks (256 tokens each); 128 threads (thread = dim)
__global__ void k_av(const float* __restrict__ vc) {
    int b = blockIdx.x;
    int h = b >> 4, ch = b & 15;
    int tid = threadIdx.x;
    __shared__ float ws[256];
    __shared__ int   ti[256];
    int jbase = h * NSEL + ch * 256;
    for (int k = tid; k < 256; k += 128) {
        ws[k] = g_w[jbase + k];
        ti[k] = g_ti[jbase + k];
    }
    __syncthreads();
    float acc = 0.f;
#pragma unroll 4
    for (int k = 0; k < 256; k++) {
        acc += ws[k] * __ldg(&vc[((long)ti[k] * 32 + h) * DDIM + tid]);
    }
    atomicAdd(&g_o[h * DDIM + tid], acc);
}

// ---------------- 6: output GEMV (split-K, atomic) ---------------------------
// grid = 32 colgroups * 16 rowgroups = 512 blocks, 128 threads
__global__ void k_out(const float* __restrict__ Wo, float* __restrict__ out) {
    int b  = blockIdx.x;
    int cg = b & 31;
    int rg = b >> 5;               // 16 rowgroups of 256 rows
    int lane = threadIdx.x & 31;
    int wrp  = threadIdx.x >> 5;   // 4 warps, 64 rows each

    __shared__ float os[256];
    for (int i = threadIdx.x; i < 256; i += 128) os[i] = g_o[rg * 256 + i];
    __syncthreads();

    long i0  = (long)rg * 256 + wrp * 64;
    int col4 = cg * 32 + lane;
    const float4* W4 = (const float4*)Wo;
    float4 acc = make_float4(0.f, 0.f, 0.f, 0.f);
#pragma unroll 8
    for (int i = 0; i < 64; i++) {
        float  xv = os[wrp * 64 + i];
        float4 wv = __ldg(&W4[(i0 + i) * 1024 + col4]);
        acc.x += xv * wv.x; acc.y += xv * wv.y;
        acc.z += xv * wv.z; acc.w += xv * wv.w;
    }
    float* dst = &out[col4 * 4];
    atomicAdd(dst + 0, acc.x); atomicAdd(dst + 1, acc.y);
    atomicAdd(dst + 2, acc.z); atomicAdd(dst + 3, acc.w);
}

// ---------------- launch ------------------------------------------------------
extern "C" void kernel_launch(void* const* d_in, const int* in_sizes, int n_in,
                              void* d_out, int out_size) {
    const float* x  = (const float*)d_in[0];
    const float* kc = (const float*)d_in[1];
    const float* vc = (const float*)d_in[2];
    const float* Wq = (const float*)d_in[3];
    const float* Wk = (const float*)d_in[4];
    const float* Wv = (const float*)d_in[5];
    const float* Wo = (const float*)d_in[6];
    float* out = (float*)d_out;

    k_init<<<48, 256>>>(out);
    k_qkv<<<768, 128>>>(x, Wq, Wk, Wv);
    k_rope<<<16, 128>>>();
    k_scan<<<8192, 256>>>(kc);
    k_sel<<<32, 256>>>();
    k_av<<<512, 128>>>(vc);
    k_out<<<512, 128>>>(Wo, out);
}

// round 5
// speedup vs baseline: 1.6147x; 1.2145x over previous
#include <cuda_runtime.h>
#include <math.h>

#define NHEAD 32
#define DDIM  128
#define KVLEN 32768
#define PAGE  16
#define NPAGE 2048
#define TOPK  256
#define NSEL  (TOPK * PAGE)          /* 4096 selected tokens per head */
#define HDIM  4096
#define SCALE 0.08838834764831845f   /* 1/sqrt(128) */

// ---------------- scratch (device globals; no allocations allowed) ----------
__device__ float g_qkv[3 * HDIM];        // q | k_new | v_new (RAW, pre-RoPE)
__device__ float g_sall[NHEAD * KVLEN];  // all scores, scaled (4 MB)
__device__ float g_est[NHEAD * NPAGE];   // page estimates
__device__ float g_w[NHEAD * NSEL];      // softmax weights of selected tokens
__device__ int   g_ti[NHEAD * NSEL];     // token ids of selected tokens
__device__ float g_o[NHEAD * DDIM];      // attention output
__device__ __align__(16) float g_cos[64];
__device__ __align__(16) float g_sin[64];

// ---------------- 0: zero atomic targets + RoPE trig table -------------------
// grid 65 x 256: blocks 0..47 zero g_qkv, 48..63 zero out, 64 computes trig
__global__ void k_pre(float* __restrict__ out) {
    int b = blockIdx.x, t = threadIdx.x;
    if (b < 48) {
        g_qkv[b * 256 + t] = 0.f;
    } else if (b < 64) {
        out[(b - 48) * 256 + t] = 0.f;
    } else if (t < 64) {
        float inv = (float)pow(10000.0, -(double)t / 64.0);
        float ang = 32768.0f * inv;
        float s, c;
        sincosf(ang, &s, &c);
        g_cos[t] = c;
        g_sin[t] = s;
    }
}

// ---------------- 1: fused QKV GEMV (split-K, atomic accumulate) ------------
// grid = 3 mats * 32 colgroups * 8 rowgroups = 768 blocks, 128 threads
__global__ void k_qkv(const float* __restrict__ x,
                      const float* __restrict__ Wq,
                      const float* __restrict__ Wk,
                      const float* __restrict__ Wv) {
    int b  = blockIdx.x;
    int m  = b >> 8;           // matrix 0..2
    int r  = b & 255;
    int cg = r & 31;           // column group (128 cols)
    int rg = r >> 5;           // row group (512 rows)
    const float* W = (m == 0) ? Wq : (m == 1) ? Wk : Wv;

    int lane = threadIdx.x & 31;
    int wrp  = threadIdx.x >> 5;   // 4 warps, 128 rows each

    __shared__ float xs[512];
    for (int i = threadIdx.x; i < 512; i += 128) xs[i] = x[rg * 512 + i];
    __syncthreads();

    int col4 = cg * 32 + lane;               // float4 column index (0..1023)
    long i0  = (long)rg * 512 + wrp * 128;
    const float4* W4 = (const float4*)W;

    float4 acc = make_float4(0.f, 0.f, 0.f, 0.f);
#pragma unroll 8
    for (int i = 0; i < 128; i++) {
        float  xv = xs[wrp * 128 + i];
        float4 wv = __ldg(&W4[(i0 + i) * 1024 + col4]);
        acc.x += xv * wv.x; acc.y += xv * wv.y;
        acc.z += xv * wv.z; acc.w += xv * wv.w;
    }
    float* dst = &g_qkv[m * HDIM + col4 * 4];
    atomicAdd(dst + 0, acc.x); atomicAdd(dst + 1, acc.y);
    atomicAdd(dst + 2, acc.z); atomicAdd(dst + 3, acc.w);
}

// ---------------- 2: page min/max + est + ALL token scores (one pass) -------
// one warp per (page, head); grid 8192 x 256 threads.
// RoPE on q applied in the prologue (rotation table + cross-lane shfl).
__global__ void k_scan(const float* __restrict__ kc) {
    int g    = blockIdx.x * 8 + (threadIdx.x >> 5);
    int lane = threadIdx.x & 31;
    int p = g >> 5, h = g & 31;

    float4 q4 = ((const float4*)g_qkv)[h * 32 + lane];   // raw q[h, lane*4..+3]
    // RoPE: dims i<64 pair with i+64; partner lives in lane^16
    float4 pq;
    pq.x = __shfl_xor_sync(0xffffffffu, q4.x, 16);
    pq.y = __shfl_xor_sync(0xffffffffu, q4.y, 16);
    pq.z = __shfl_xor_sync(0xffffffffu, q4.z, 16);
    pq.w = __shfl_xor_sync(0xffffffffu, q4.w, 16);
    int ai = (lane & 15) * 4;
    float4 cc = *(const float4*)&g_cos[ai];
    float4 ss = *(const float4*)&g_sin[ai];
    if (lane < 16) {
        q4.x = q4.x * cc.x - pq.x * ss.x;
        q4.y = q4.y * cc.y - pq.y * ss.y;
        q4.z = q4.z * cc.z - pq.z * ss.z;
        q4.w = q4.w * cc.w - pq.w * ss.w;
    } else {
        q4.x = q4.x * cc.x + pq.x * ss.x;
        q4.y = q4.y * cc.y + pq.y * ss.y;
        q4.z = q4.z * cc.z + pq.z * ss.z;
        q4.w = q4.w * cc.w + pq.w * ss.w;
    }

    const float4* k4 = (const float4*)kc;
    long base = ((long)p * 16 * 32 + h) * 32;            // float4 offset
    float4 mn = make_float4(0, 0, 0, 0), mx = mn;

#pragma unroll
    for (int t = 0; t < 16; t++) {
        float4 kv = __ldg(&k4[base + (long)t * 1024 + lane]);
        if (t == 0) { mn = kv; mx = kv; }
        else {
            mn.x = fminf(mn.x, kv.x); mn.y = fminf(mn.y, kv.y);
            mn.z = fminf(mn.z, kv.z); mn.w = fminf(mn.w, kv.w);
            mx.x = fmaxf(mx.x, kv.x); mx.y = fmaxf(mx.y, kv.y);
            mx.z = fmaxf(mx.z, kv.z); mx.w = fmaxf(mx.w, kv.w);
        }
        float d = q4.x * kv.x + q4.y * kv.y + q4.z * kv.z + q4.w * kv.w;
#pragma unroll
        for (int o = 16; o > 0; o >>= 1) d += __shfl_xor_sync(0xffffffffu, d, o);
        if (lane == 0) g_sall[h * KVLEN + p * 16 + t] = d * SCALE;
    }
    float e = fmaxf(q4.x * mn.x, q4.x * mx.x) + fmaxf(q4.y * mn.y, q4.y * mx.y)
            + fmaxf(q4.z * mn.z, q4.z * mx.z) + fmaxf(q4.w * mn.w, q4.w * mx.w);
#pragma unroll
    for (int o = 16; o > 0; o >>= 1) e += __shfl_xor_sync(0xffffffffu, e, o);
    if (lane == 0) g_est[h * NPAGE + p] = e;
}

// ---------------- 3: fused top-256 (parallel radix select) + softmax ---------
// 32 blocks (one per head) x 1024 threads
__global__ void __launch_bounds__(1024) k_sel() {
    int h = blockIdx.x, tid = threadIdx.x;
    __shared__ unsigned keys[NPAGE];    // 8 KB
    __shared__ int      cnt[256];
    __shared__ float    sval[NSEL];     // 16 KB
    __shared__ int      sel[TOPK];
    __shared__ float    red[1024];
    __shared__ unsigned sh_prefix;
    __shared__ int      sh_krem, sh_base;

    // load est -> order-preserving uint keys (descending fp == descending uint)
    for (int i = tid; i < NPAGE; i += 1024) {
        unsigned u = __float_as_uint(g_est[h * NPAGE + i]);
        keys[i] = (u & 0x80000000u) ? ~u : (u | 0x80000000u);
    }
    if (tid == 0) { sh_prefix = 0u; sh_krem = TOPK; sh_base = 0; }
    if (tid < 256) cnt[tid] = 0;
    __syncthreads();

    // 4-round radix select: find T = 256th-largest key
#pragma unroll
    for (int shift = 24; shift >= 0; shift -= 8) {
        unsigned pmask = (shift == 24) ? 0u : (0xFFFFFFFFu << (shift + 8));
        unsigned pfx = sh_prefix;
        int krem = sh_krem;
        for (int i = tid; i < NPAGE; i += 1024)
            if ((keys[i] & pmask) == pfx)
                atomicAdd(&cnt[(keys[i] >> shift) & 255], 1);
        __syncthreads();
        // warp 0: suffix-inclusive sum over 256 bins (8 bins/lane + shfl scan)
        if (tid < 32) {
            int b0[8];
#pragma unroll
            for (int j = 0; j < 8; j++) b0[j] = cnt[tid * 8 + j];
#pragma unroll
            for (int j = 6; j >= 0; j--) b0[j] += b0[j + 1];
            int tot = b0[0], suf = tot;
#pragma unroll
            for (int off = 1; off < 32; off <<= 1) {
                int v = __shfl_down_sync(0xffffffffu, suf, off);
                if (tid + off < 32) suf += v;
            }
            int excl = suf - tot;
#pragma unroll
            for (int j = 0; j < 8; j++) cnt[tid * 8 + j] = b0[j] + excl;
        }
        __syncthreads();
        // exactly one bin d satisfies S[d+1] < krem <= S[d]
        if (tid < 256) {
            int S     = cnt[tid];
            int Snext = (tid < 255) ? cnt[tid + 1] : 0;
            if (Snext < krem && krem <= S) {
                sh_prefix = pfx | ((unsigned)tid << shift);
                sh_krem   = krem - Snext;
            }
        }
        __syncthreads();
        if (tid < 256) cnt[tid] = 0;   // reset for next round
        __syncthreads();
    }
    unsigned T = sh_prefix;

    // collect strictly-greater (all belong), then pad with ties (capped)
    for (int i = tid; i < NPAGE; i += 1024)
        if (keys[i] > T) sel[atomicAdd(&sh_base, 1)] = i;
    __syncthreads();
    for (int i = tid; i < NPAGE; i += 1024)
        if (keys[i] == T) {
            int p = atomicAdd(&sh_base, 1);
            if (p < TOPK) sel[p] = i;
        }
    __syncthreads();

    // s_new = (q . k_new) * SCALE  (RoPE is a rotation: dot is invariant, use raw)
    red[tid] = (tid < 128) ? g_qkv[h * DDIM + tid] * g_qkv[HDIM + h * DDIM + tid] : 0.f;
    __syncthreads();
    for (int o = 512; o > 0; o >>= 1) {
        if (tid < o) red[tid] += red[tid + o];
        __syncthreads();
    }
    float s_new = red[0] * SCALE;
    __syncthreads();

    // gather the 4096 selected scores into shared
    for (int j = tid; j < NSEL; j += 1024)
        sval[j] = g_sall[h * KVLEN + sel[j >> 4] * 16 + (j & 15)];
    __syncthreads();

    // max
    float lm = s_new;
    for (int j = tid; j < NSEL; j += 1024) lm = fmaxf(lm, sval[j]);
    red[tid] = lm;
    __syncthreads();
    for (int o = 512; o > 0; o >>= 1) {
        if (tid < o) red[tid] = fmaxf(red[tid], red[tid + o]);
        __syncthreads();
    }
    float m = red[0];
    __syncthreads();

    // Z
    float z = (tid == 0) ? expf(s_new - m) : 0.f;
    for (int j = tid; j < NSEL; j += 1024) z += expf(sval[j] - m);
    red[tid] = z;
    __syncthreads();
    for (int o = 512; o > 0; o >>= 1) {
        if (tid < o) red[tid] += red[tid + o];
        __syncthreads();
    }
    float zi = 1.f / red[0];
    __syncthreads();

    // emit weights + token ids; init o with new-token contribution
    for (int j = tid; j < NSEL; j += 1024) {
        g_w[h * NSEL + j]  = expf(sval[j] - m) * zi;
        g_ti[h * NSEL + j] = sel[j >> 4] * 16 + (j & 15);
    }
    if (tid < 128)
        g_o[h * DDIM + tid] = expf(s_new - m) * zi * g_qkv[2 * HDIM + h * DDIM + tid];
}

// ---------------- 4: weighted V gather-accumulate ----------------------------
// grid = 32 heads * 32 chunks (128 tokens each); 256 threads
// thread = (dim, token-parity): 2 rows in flight per iteration, unroll 8
__global__ void __launch_bounds__(256) k_av(const float* __restrict__ vc) {
    int b = blockIdx.x;
    int h = b >> 5, ch = b & 31;
    int tid = threadIdx.x;
    int dim = tid & 127, half = tid >> 7;
    __shared__ float ws[128];
    __shared__ int   ti[128];
    __shared__ float sacc[256];
    int jbase = h * NSEL + ch * 128;
    if (tid < 128) {
        ws[tid] = g_w[jbase + tid];
        ti[tid] = g_ti[jbase + tid];
    }
    __syncthreads();
    float acc = 0.f;
#pragma unroll 8
    for (int k = half; k < 128; k += 2) {
        acc += ws[k] * __ldg(&vc[((long)ti[k] * 32 + h) * DDIM + dim]);
    }
    sacc[tid] = acc;
    __syncthreads();
    if (tid < 128)
        atomicAdd(&g_o[h * DDIM + tid], sacc[tid] + sacc[tid + 128]);
}

// ---------------- 5: output GEMV (split-K, atomic) ---------------------------
// grid = 32 colgroups * 16 rowgroups = 512 blocks, 128 threads
__global__ void k_out(const float* __restrict__ Wo, float* __restrict__ out) {
    int b  = blockIdx.x;
    int cg = b & 31;
    int rg = b >> 5;               // 16 rowgroups of 256 rows
    int lane = threadIdx.x & 31;
    int wrp  = threadIdx.x >> 5;   // 4 warps, 64 rows each

    __shared__ float os[256];
    for (int i = threadIdx.x; i < 256; i += 128) os[i] = g_o[rg * 256 + i];
    __syncthreads();

    long i0  = (long)rg * 256 + wrp * 64;
    int col4 = cg * 32 + lane;
    const float4* W4 = (const float4*)Wo;
    float4 acc = make_float4(0.f, 0.f, 0.f, 0.f);
#pragma unroll 8
    for (int i = 0; i < 64; i++) {
        float  xv = os[wrp * 64 + i];
        float4 wv = __ldg(&W4[(i0 + i) * 1024 + col4]);
        acc.x += xv * wv.x; acc.y += xv * wv.y;
        acc.z += xv * wv.z; acc.w += xv * wv.w;
    }
    float* dst = &out[col4 * 4];
    atomicAdd(dst + 0, acc.x); atomicAdd(dst + 1, acc.y);
    atomicAdd(dst + 2, acc.z); atomicAdd(dst + 3, acc.w);
}

// ---------------- launch ------------------------------------------------------
extern "C" void kernel_launch(void* const* d_in, const int* in_sizes, int n_in,
                              void* d_out, int out_size) {
    const float* x  = (const float*)d_in[0];
    const float* kc = (const float*)d_in[1];
    const float* vc = (const float*)d_in[2];
    const float* Wq = (const float*)d_in[3];
    const float* Wk = (const float*)d_in[4];
    const float* Wv = (const float*)d_in[5];
    const float* Wo = (const float*)d_in[6];
    float* out = (float*)d_out;

    k_pre<<<65, 256>>>(out);
    k_qkv<<<768, 128>>>(x, Wq, Wk, Wv);
    k_scan<<<8192, 256>>>(kc);
    k_sel<<<32, 1024>>>();
    k_av<<<1024, 256>>>(vc);
    k_out<<<512, 128>>>(Wo, out);
}

// round 6
// speedup vs baseline: 1.6171x; 1.0015x over previous
#include <cuda_runtime.h>
#include <math.h>

#define NHEAD 32
#define DDIM  128
#define KVLEN 32768
#define PAGE  16
#define NPAGE 2048
#define TOPK  256
#define NSEL  (TOPK * PAGE)          /* 4096 selected tokens per head */
#define HDIM  4096
#define SCALE 0.08838834764831845f   /* 1/sqrt(128) */

// ---------------- scratch (device globals; no allocations allowed) ----------
__device__ float g_qkv[3 * HDIM];        // q | k_new | v_new (RAW, pre-RoPE)
__device__ float g_sall[NHEAD * KVLEN];  // all scores, scaled (4 MB)
__device__ float g_est[NHEAD * NPAGE];   // page estimates
__device__ int   g_selp[NHEAD * TOPK];   // selected page ids
__device__ float g_m[NHEAD];             // softmax max
__device__ float g_zinv[NHEAD];          // 1/Z
__device__ float g_o[NHEAD * DDIM];      // attention output
__device__ __align__(16) float g_cos[64];
__device__ __align__(16) float g_sin[64];

// ---------------- 0: zero atomic targets + RoPE trig table -------------------
// grid 65 x 256: blocks 0..47 zero g_qkv, 48..63 zero out, 64 computes trig
__global__ void k_pre(float* __restrict__ out) {
    int b = blockIdx.x, t = threadIdx.x;
    if (b < 48) {
        g_qkv[b * 256 + t] = 0.f;
    } else if (b < 64) {
        out[(b - 48) * 256 + t] = 0.f;
    } else if (t < 64) {
        float inv = (float)pow(10000.0, -(double)t / 64.0);
        float ang = 32768.0f * inv;
        float s, c;
        sincosf(ang, &s, &c);
        g_cos[t] = c;
        g_sin[t] = s;
    }
}

// ---------------- 1: fused QKV GEMV (split-K, atomic accumulate) ------------
// grid = 3 mats * 32 colgroups * 8 rowgroups = 768 blocks, 128 threads
__global__ void k_qkv(const float* __restrict__ x,
                      const float* __restrict__ Wq,
                      const float* __restrict__ Wk,
                      const float* __restrict__ Wv) {
    int b  = blockIdx.x;
    int m  = b >> 8;           // matrix 0..2
    int r  = b & 255;
    int cg = r & 31;           // column group (128 cols)
    int rg = r >> 5;           // row group (512 rows)
    const float* W = (m == 0) ? Wq : (m == 1) ? Wk : Wv;

    int lane = threadIdx.x & 31;
    int wrp  = threadIdx.x >> 5;   // 4 warps, 128 rows each

    __shared__ float xs[512];
    for (int i = threadIdx.x; i < 512; i += 128) xs[i] = x[rg * 512 + i];
    __syncthreads();

    int col4 = cg * 32 + lane;               // float4 column index (0..1023)
    long i0  = (long)rg * 512 + wrp * 128;
    const float4* W4 = (const float4*)W;

    float4 acc = make_float4(0.f, 0.f, 0.f, 0.f);
#pragma unroll 8
    for (int i = 0; i < 128; i++) {
        float  xv = xs[wrp * 128 + i];
        float4 wv = __ldg(&W4[(i0 + i) * 1024 + col4]);
        acc.x += xv * wv.x; acc.y += xv * wv.y;
        acc.z += xv * wv.z; acc.w += xv * wv.w;
    }
    float* dst = &g_qkv[m * HDIM + col4 * 4];
    atomicAdd(dst + 0, acc.x); atomicAdd(dst + 1, acc.y);
    atomicAdd(dst + 2, acc.z); atomicAdd(dst + 3, acc.w);
}

// ---------------- 2: page min/max + est + ALL token scores (one pass) -------
// one warp per (page, head); grid 8192 x 256 threads.
// RoPE on q applied in the prologue (rotation table + cross-lane shfl).
__global__ void k_scan(const float* __restrict__ kc) {
    int g    = blockIdx.x * 8 + (threadIdx.x >> 5);
    int lane = threadIdx.x & 31;
    int p = g >> 5, h = g & 31;

    float4 q4 = ((const float4*)g_qkv)[h * 32 + lane];   // raw q[h, lane*4..+3]
    // RoPE: dims i<64 pair with i+64; partner lives in lane^16
    float4 pq;
    pq.x = __shfl_xor_sync(0xffffffffu, q4.x, 16);
    pq.y = __shfl_xor_sync(0xffffffffu, q4.y, 16);
    pq.z = __shfl_xor_sync(0xffffffffu, q4.z, 16);
    pq.w = __shfl_xor_sync(0xffffffffu, q4.w, 16);
    int ai = (lane & 15) * 4;
    float4 cc = *(const float4*)&g_cos[ai];
    float4 ss = *(const float4*)&g_sin[ai];
    if (lane < 16) {
        q4.x = q4.x * cc.x - pq.x * ss.x;
        q4.y = q4.y * cc.y - pq.y * ss.y;
        q4.z = q4.z * cc.z - pq.z * ss.z;
        q4.w = q4.w * cc.w - pq.w * ss.w;
    } else {
        q4.x = q4.x * cc.x + pq.x * ss.x;
        q4.y = q4.y * cc.y + pq.y * ss.y;
        q4.z = q4.z * cc.z + pq.z * ss.z;
        q4.w = q4.w * cc.w + pq.w * ss.w;
    }

    const float4* k4 = (const float4*)kc;
    long base = ((long)p * 16 * 32 + h) * 32;            // float4 offset
    float4 mn = make_float4(0, 0, 0, 0), mx = mn;

#pragma unroll
    for (int t = 0; t < 16; t++) {
        float4 kv = __ldg(&k4[base + (long)t * 1024 + lane]);
        if (t == 0) { mn = kv; mx = kv; }
        else {
            mn.x = fminf(mn.x, kv.x); mn.y = fminf(mn.y, kv.y);
            mn.z = fminf(mn.z, kv.z); mn.w = fminf(mn.w, kv.w);
            mx.x = fmaxf(mx.x, kv.x); mx.y = fmaxf(mx.y, kv.y);
            mx.z = fmaxf(mx.z, kv.z); mx.w = fmaxf(mx.w, kv.w);
        }
        float d = q4.x * kv.x + q4.y * kv.y + q4.z * kv.z + q4.w * kv.w;
#pragma unroll
        for (int o = 16; o > 0; o >>= 1) d += __shfl_xor_sync(0xffffffffu, d, o);
        if (lane == 0) g_sall[h * KVLEN + p * 16 + t] = d * SCALE;
    }
    float e = fmaxf(q4.x * mn.x, q4.x * mx.x) + fmaxf(q4.y * mn.y, q4.y * mx.y)
            + fmaxf(q4.z * mn.z, q4.z * mx.z) + fmaxf(q4.w * mn.w, q4.w * mx.w);
#pragma unroll
    for (int o = 16; o > 0; o >>= 1) e += __shfl_xor_sync(0xffffffffu, e, o);
    if (lane == 0) g_est[h * NPAGE + p] = e;
}

// ---------------- 3: top-256 select + softmax stats (no weight emission) -----
// 32 blocks (one per head) x 1024 threads
__global__ void __launch_bounds__(1024) k_sel() {
    int h = blockIdx.x, tid = threadIdx.x;
    int lane = tid & 31, wid = tid >> 5;
    __shared__ unsigned keys[NPAGE];    // 8 KB
    __shared__ int      cnt[256];
    __shared__ float    sval[NSEL];     // 16 KB
    __shared__ int      sel[TOPK];
    __shared__ float    wred[32];
    __shared__ unsigned sh_prefix;
    __shared__ int      sh_krem, sh_base;
    __shared__ float    sh_m, sh_snew;

    // load est -> order-preserving uint keys (descending fp == descending uint)
    for (int i = tid; i < NPAGE; i += 1024) {
        unsigned u = __float_as_uint(g_est[h * NPAGE + i]);
        keys[i] = (u & 0x80000000u) ? ~u : (u | 0x80000000u);
    }
    if (tid == 0) { sh_prefix = 0u; sh_krem = TOPK; sh_base = 0; }
    if (tid < 256) cnt[tid] = 0;
    __syncthreads();

    // 4-round radix select: find T = 256th-largest key
#pragma unroll
    for (int shift = 24; shift >= 0; shift -= 8) {
        unsigned pmask = (shift == 24) ? 0u : (0xFFFFFFFFu << (shift + 8));
        unsigned pfx = sh_prefix;
        int krem = sh_krem;
        for (int i = tid; i < NPAGE; i += 1024)
            if ((keys[i] & pmask) == pfx)
                atomicAdd(&cnt[(keys[i] >> shift) & 255], 1);
        __syncthreads();
        // warp 0: suffix-inclusive sum over 256 bins (8 bins/lane + shfl scan)
        if (tid < 32) {
            int b0[8];
#pragma unroll
            for (int j = 0; j < 8; j++) b0[j] = cnt[tid * 8 + j];
#pragma unroll
            for (int j = 6; j >= 0; j--) b0[j] += b0[j + 1];
            int tot = b0[0], suf = tot;
#pragma unroll
            for (int off = 1; off < 32; off <<= 1) {
                int v = __shfl_down_sync(0xffffffffu, suf, off);
                if (tid + off < 32) suf += v;
            }
            int excl = suf - tot;
#pragma unroll
            for (int j = 0; j < 8; j++) cnt[tid * 8 + j] = b0[j] + excl;
        }
        __syncthreads();
        // exactly one bin d satisfies S[d+1] < krem <= S[d]
        if (tid < 256) {
            int S     = cnt[tid];
            int Snext = (tid < 255) ? cnt[tid + 1] : 0;
            if (Snext < krem && krem <= S) {
                sh_prefix = pfx | ((unsigned)tid << shift);
                sh_krem   = krem - Snext;
            }
        }
        __syncthreads();
        if (tid < 256) cnt[tid] = 0;   // reset for next round
        __syncthreads();
    }
    unsigned T = sh_prefix;

    // collect strictly-greater (all belong), then pad with ties (capped)
    for (int i = tid; i < NPAGE; i += 1024)
        if (keys[i] > T) sel[atomicAdd(&sh_base, 1)] = i;
    __syncthreads();
    for (int i = tid; i < NPAGE; i += 1024)
        if (keys[i] == T) {
            int p = atomicAdd(&sh_base, 1);
            if (p < TOPK) sel[p] = i;
        }
    __syncthreads();

    // s_new = (q . k_new) * SCALE  (RoPE is a rotation: dot is invariant)
    {
        float v = (tid < 128) ? g_qkv[h * DDIM + tid] * g_qkv[HDIM + h * DDIM + tid] : 0.f;
#pragma unroll
        for (int o = 16; o > 0; o >>= 1) v += __shfl_xor_sync(0xffffffffu, v, o);
        if (lane == 0) wred[wid] = v;
        __syncthreads();
        if (tid == 0) {
            float s = wred[0] + wred[1] + wred[2] + wred[3];
            sh_snew = s * SCALE;
        }
        __syncthreads();
    }
    float s_new = sh_snew;

    // gather the 4096 selected scores into shared
    for (int j = tid; j < NSEL; j += 1024)
        sval[j] = g_sall[h * KVLEN + sel[j >> 4] * 16 + (j & 15)];
    __syncthreads();

    // max (shfl-based reduction)
    {
        float lm = s_new;
        for (int j = tid; j < NSEL; j += 1024) lm = fmaxf(lm, sval[j]);
#pragma unroll
        for (int o = 16; o > 0; o >>= 1)
            lm = fmaxf(lm, __shfl_xor_sync(0xffffffffu, lm, o));
        if (lane == 0) wred[wid] = lm;
        __syncthreads();
        if (tid < 32) {
            float v = wred[tid];
#pragma unroll
            for (int o = 16; o > 0; o >>= 1)
                v = fmaxf(v, __shfl_xor_sync(0xffffffffu, v, o));
            if (tid == 0) sh_m = v;
        }
        __syncthreads();
    }
    float m = sh_m;

    // Z (shfl-based reduction)
    {
        float z = (tid == 0) ? expf(s_new - m) : 0.f;
        for (int j = tid; j < NSEL; j += 1024) z += expf(sval[j] - m);
#pragma unroll
        for (int o = 16; o > 0; o >>= 1) z += __shfl_xor_sync(0xffffffffu, z, o);
        if (lane == 0) wred[wid] = z;
        __syncthreads();
        if (tid < 32) {
            float v = wred[tid];
#pragma unroll
            for (int o = 16; o > 0; o >>= 1) v += __shfl_xor_sync(0xffffffffu, v, o);
            if (tid == 0) {
                g_m[h]    = m;
                g_zinv[h] = 1.f / v;
            }
        }
        __syncthreads();
    }

    // emit selected pages; init o with new-token contribution
    if (tid < TOPK) g_selp[h * TOPK + tid] = sel[tid];
    if (tid < 128) {
        float zi = g_zinv[h];
        g_o[h * DDIM + tid] = expf(s_new - m) * zi * g_qkv[2 * HDIM + h * DDIM + tid];
    }
}

// ---------------- 4: weighted V gather-accumulate (weights computed inline) --
// grid = 32 heads * 32 chunks (8 pages = 128 tokens each); 256 threads
__global__ void __launch_bounds__(256) k_av(const float* __restrict__ vc) {
    int b = blockIdx.x;
    int h = b >> 5, ch = b & 31;
    int tid = threadIdx.x;
    int dim = tid & 127, half = tid >> 7;
    __shared__ float ws[128];
    __shared__ int   ti[128];
    __shared__ float sacc[256];
    float m  = g_m[h];
    float zi = g_zinv[h];
    if (tid < 128) {
        int page = g_selp[h * TOPK + ch * 8 + (tid >> 4)];
        int tok  = page * 16 + (tid & 15);
        ti[tid] = tok;
        ws[tid] = expf(g_sall[h * KVLEN + tok] - m) * zi;
    }
    __syncthreads();
    float acc = 0.f;
#pragma unroll 8
    for (int k = half; k < 128; k += 2) {
        acc += ws[k] * __ldg(&vc[((long)ti[k] * 32 + h) * DDIM + dim]);
    }
    sacc[tid] = acc;
    __syncthreads();
    if (tid < 128)
        atomicAdd(&g_o[h * DDIM + tid], sacc[tid] + sacc[tid + 128]);
}

// ---------------- 5: output GEMV (split-K, atomic) ---------------------------
// grid = 32 colgroups * 16 rowgroups = 512 blocks, 128 threads
__global__ void k_out(const float* __restrict__ Wo, float* __restrict__ out) {
    int b  = blockIdx.x;
    int cg = b & 31;
    int rg = b >> 5;               // 16 rowgroups of 256 rows
    int lane = threadIdx.x & 31;
    int wrp  = threadIdx.x >> 5;   // 4 warps, 64 rows each

    __shared__ float os[256];
    for (int i = threadIdx.x; i < 256; i += 128) os[i] = g_o[rg * 256 + i];
    __syncthreads();

    long i0  = (long)rg * 256 + wrp * 64;
    int col4 = cg * 32 + lane;
    const float4* W4 = (const float4*)Wo;
    float4 acc = make_float4(0.f, 0.f, 0.f, 0.f);
#pragma unroll 8
    for (int i = 0; i < 64; i++) {
        float  xv = os[wrp * 64 + i];
        float4 wv = __ldg(&W4[(i0 + i) * 1024 + col4]);
        acc.x += xv * wv.x; acc.y += xv * wv.y;
        acc.z += xv * wv.z; acc.w += xv * wv.w;
    }
    float* dst = &out[col4 * 4];
    atomicAdd(dst + 0, acc.x); atomicAdd(dst + 1, acc.y);
    atomicAdd(dst + 2, acc.z); atomicAdd(dst + 3, acc.w);
}

// ---------------- launch ------------------------------------------------------
extern "C" void kernel_launch(void* const* d_in, const int* in_sizes, int n_in,
                              void* d_out, int out_size) {
    const float* x  = (const float*)d_in[0];
    const float* kc = (const float*)d_in[1];
    const float* vc = (const float*)d_in[2];
    const float* Wq = (const float*)d_in[3];
    const float* Wk = (const float*)d_in[4];
    const float* Wv = (const float*)d_in[5];
    const float* Wo = (const float*)d_in[6];
    float* out = (float*)d_out;

    k_pre<<<65, 256>>>(out);
    k_qkv<<<768, 128>>>(x, Wq, Wk, Wv);
    k_scan<<<8192, 256>>>(kc);
    k_sel<<<32, 1024>>>();
    k_av<<<1024, 256>>>(vc);
    k_out<<<512, 128>>>(Wo, out);
}